// round 12
// baseline (speedup 1.0000x reference)
#include <cuda_runtime.h>
#include <cstdint>

// ConstituencyMFVI: B=8, N=192, 3 mean-field iterations.
// q[b,i,j] = s_span[b,i,j] + (j>i) * sum_{k != i, k != j} sigmoid(q[b,i,k]) * s_pair[b,i,j,k]
// out = sigmoid(q).
//
// R12 = R11 skeleton (148 persistent CTAs x 384 threads, reg-resident half
// rows, 3 rotating cp.async staging buffers) plus:
//  - fma.rn.f32x2 packed FMAs (halves the FMA issue floor)
//  - redundant combine: both half-threads of a row compute q/sigma (12-warp
//    tail instead of 6); sig double-buffered, h1 does the out stores
//  - prefetch.global.L2 of tile n+3 each loop: ~2 tiles of DRAM depth beyond
//    what SMEM can stage, so the stream keeps running during compute
//  - serpentine tile deal (byte-balanced across CTAs to ~1%)
// Rows j<=i never loaded (mask analytic): 113MB total HBM.

namespace {
constexpr int NN      = 192;
constexpr int HALF    = 96;
constexpr int CH      = 24;           // float4 chunks per half row
constexpr int PADH    = 100;          // half-row stride (conflict-min LDS.128)
constexpr int BROWS   = 191;          // buffer rows (rows 1..191, slot=row-1)
constexpr int THREADS = 384;
constexpr int NSM     = 148;
constexpr int NTILES  = 1536;
constexpr int HB      = BROWS * PADH; // floats per half buffer (19100)
// 3 buffers + sig[2][192] + part[384]
constexpr int SMEM_BYTES = (3 * HB + 2 * NN + 2 * NN) * 4;   // 232,272 <= 232,448
}

__device__ __forceinline__ float sigmoidf(float x) {
    return 1.0f / (1.0f + __expf(-x));
}

union F4U {                       // float4 <-> 2x f32x2 (64-bit lanes)
    float4 f;
    unsigned long long u[2];
};

__device__ __forceinline__ void fma2(unsigned long long& acc,
                                     unsigned long long a,
                                     unsigned long long b) {
    asm("fma.rn.f32x2 %0, %1, %2, %0;" : "+l"(acc) : "l"(a), "l"(b));
}
__device__ __forceinline__ float sum2(unsigned long long v) {
    return __uint_as_float((unsigned)(v & 0xffffffffu)) +
           __uint_as_float((unsigned)(v >> 32));
}

__global__ __launch_bounds__(THREADS, 1)
void mfvi_kernel(const float* __restrict__ s_span,
                 const float* __restrict__ s_pair,
                 float* __restrict__ out)
{
    extern __shared__ float smf[];
    float* bufs = smf;                  // 3 x [191][PADH]
    float* sig  = smf + 3 * HB;         // [2][192]
    float* part = sig + 2 * NN;         // [384]: low partials [0..191], high [192..383]

    const int s  = blockIdx.x;
    const int t  = threadIdx.x;
    const bool h0 = t < NN;             // low-half threads
    const int jj = h0 ? t : t - NN;     // my row
    const int m  = (s < 56) ? 11 : 10;  // tiles for this CTA

    const int rr0 = t / CH;             // 0..15
    const int cc0 = t % CH;

    // serpentine deal: byte-balanced to ~1% across CTAs
    auto g_of = [&](int n) { return n * NSM + ((n & 1) ? (NSM - 1 - s) : s); };

    // issue one half (xoff 0 or 96) of tile n into buffer bi; ALWAYS 1 commit.
    auto issue_half = [&](int bi, int n, int xoff) {
        if (n < m) {
            int g = g_of(n);
            int i = g >> 3;
            int R = NN - 1 - i;
            const float* gP = s_pair + (size_t)((g & 7) * NN + i) * (NN * NN);
            uint32_t sb = (uint32_t)__cvta_generic_to_shared(bufs + bi * HB);
            for (int rr = rr0; rr < R; rr += 16) {
                int row = i + 1 + rr;
                uint32_t dst = sb + (uint32_t)((i + rr) * PADH + cc0 * 4) * 4u;
                const float* src = gP + (size_t)row * NN + xoff + cc0 * 4;
                asm volatile("cp.async.cg.shared.global [%0], [%1], 16;\n"
                             :: "r"(dst), "l"(src));
            }
        }
        asm volatile("cp.async.commit_group;\n");
    };

    // L2-prefetch the whole active-row range of tile n (contiguous bytes)
    auto prefetch_tile = [&](int n) {
        if (n >= m) return;
        int g = g_of(n);
        int i = g >> 3;
        int R = NN - 1 - i;
        if (R <= 0) return;
        const char* p0 = (const char*)(s_pair
                         + (size_t)((g & 7) * NN + i) * (NN * NN)
                         + (size_t)(i + 1) * NN);
        int nl = R * 6;                 // 128B lines
        for (int x = t; x < nl; x += THREADS)
            asm volatile("prefetch.global.L2 [%0];" :: "l"(p0 + (size_t)x * 128));
    };

    // ---- prologue: L0 -> buf0, H0 -> buf1, L1 -> buf2; prefetch tile 2 ----
    issue_half(0, 0, 0);
    issue_half(1, 0, HALF);
    issue_half(2, 1, 0);
    prefetch_tile(2);

    F4U r[CH];

    #pragma unroll 1
    for (int n = 0; n < m; n++) {
        const int g  = g_of(n);
        const int i  = g >> 3;
        const int tz = (g & 7) * NN + i;
        const int bl = (2 * n) % 3;
        const int bh = (2 * n + 1) % 3;
        const bool act = jj > i;

        // ---- both halves of tile n resident (only L(n+1) may be pending) ----
        asm volatile("cp.async.wait_group 1;\n");
        __syncthreads();

        // copy my half row to regs; grab per-row scalars (BOTH half-threads)
        float sv = 0.0f, ex_i = 0.0f, ex_j = 0.0f;
        {
            float sval = s_span[(size_t)tz * NN + jj];
            if (!act) {                          // constant rows
                float v = sigmoidf(sval);
                if (h0) { sig[jj] = v; sig[NN + jj] = v; }
                else    { out[(size_t)tz * NN + jj] = v; }
            } else {
                sv = sval;
                if (h0) sig[jj] = sigmoidf(sval);        // sigma^0 -> buffer 0
                const int slot = jj - 1;
                const float* Lrow = bufs + bl * HB + slot * PADH;
                const float* Hrow = bufs + bh * HB + slot * PADH;
                ex_i = (i  < HALF) ? Lrow[i]  : Hrow[i  - HALF];  // P[j, i]
                ex_j = (jj < HALF) ? Lrow[jj] : Hrow[jj - HALF];  // P[j, j]
                const float4* r4 = reinterpret_cast<const float4*>(
                    bufs + (h0 ? bl : bh) * HB + slot * PADH);
                #pragma unroll
                for (int c = 0; c < CH; c++) r[c].f = r4[c];
            }
        }
        __syncthreads();                         // copies + sig init done -> buffers free

        issue_half(bl, n + 1, HALF);             // H(n+1)
        issue_half(bh, n + 2, 0);                // L(n+2)
        prefetch_tile(n + 3);                    // DRAM depth beyond SMEM

        #pragma unroll 1
        for (int it = 0; it < 3; it++) {
            const float* sigA = sig + (it & 1) * NN;          // read buffer
            float* sigB = sig + (((it & 1) ^ 1)) * NN;        // write buffer
            if (act) {
                const float4* sg4 = reinterpret_cast<const float4*>(sigA) + (h0 ? 0 : CH);
                unsigned long long a0 = 0, a1 = 0, a2 = 0, a3 = 0;
                #pragma unroll
                for (int c = 0; c < CH; c += 2) {
                    F4U sg;  sg.f = sg4[c];
                    fma2(a0, r[c].u[0], sg.u[0]);
                    fma2(a1, r[c].u[1], sg.u[1]);
                    F4U sg2; sg2.f = sg4[c + 1];
                    fma2(a2, r[c + 1].u[0], sg2.u[0]);
                    fma2(a3, r[c + 1].u[1], sg2.u[1]);
                }
                part[t < NN ? jj : NN + jj] = (sum2(a0) + sum2(a1)) + (sum2(a2) + sum2(a3));
            }
            __syncthreads();                     // partials published; sigA reads done
            if (act) {
                float q = sv + part[jj] + part[NN + jj]
                        - sigA[i] * ex_i - sigA[jj] * ex_j;
                float v = sigmoidf(q);
                if (it < 2) { if (h0) sigB[jj] = v; }
                else        { if (!h0) out[(size_t)tz * NN + jj] = v; }
            }
            __syncthreads();                     // sigB stable / tile teardown safe
        }
    }
}

extern "C" void kernel_launch(void* const* d_in, const int* in_sizes, int n_in,
                              void* d_out, int out_size)
{
    const float* s_span = (const float*)d_in[0];
    const float* s_pair = (const float*)d_in[1];
    float* out = (float*)d_out;

    cudaFuncSetAttribute(mfvi_kernel,
                         cudaFuncAttributeMaxDynamicSharedMemorySize, SMEM_BYTES);

    mfvi_kernel<<<NSM, THREADS, SMEM_BYTES>>>(s_span, s_pair, out);
}